// round 13
// baseline (speedup 1.0000x reference)
#include <cuda_runtime.h>

#define NP   16     // B*K problems
#define N    2048   // points per cloud
#define JC1  32     // j-chunks, chain 1 (CP=4)
#define JCH1 (N / JC1)
#define JC2  16     // j-chunks, chain 2 (CP=12)
#define JCH2 (N / JC2)
#define SJ   16     // j rows per cp.async stage
#define NS1  (JCH1 / SJ)   // 4 stages, chain 1
#define NS2  (JCH2 / SJ)   // 8 stages, chain 2

// ---------------- scratch (__device__ globals: allocation-free) ----------------
__device__ float4        g_Xs[NP][N];               // scaled points + squared norm
__device__ unsigned char g_W8[NP][N][N];            // q=round(127*w), u8, diag=0; transposed (i fastest)
__device__ float         g_s[NP][N];                // s_i = 0.5/(127*deg_i)  (dequant folded in)
__device__ float         g_d[NP][N];                // d_i = 0.5 + 0.5/deg_i  (exact diagonal of P)
__device__ float         g_F[NP][N * 4];            // chain-1 t=0 (x,y,z,0)
__device__ float         g_U[NP][N * 12];           // chain-2 t=0 (first 12 cols of U)
__device__ float         g_p1[17][JC1][NP][N * 4];  // chain-1 per-step j-chunk partials
__device__ float         g_p2[17][JC2][NP][N * 12]; // chain-2 per-step j-chunk partials

// ---------------- helpers ----------------
__device__ __forceinline__ unsigned long long pack2(float a) {
    unsigned long long r;
    asm("mov.b64 %0, {%1, %1};" : "=l"(r) : "f"(a));
    return r;
}
__device__ __forceinline__ unsigned long long mkpair(float lo, float hi) {
    unsigned long long r;
    asm("mov.b64 %0, {%1, %2};" : "=l"(r) : "f"(lo), "f"(hi));
    return r;
}
__device__ __forceinline__ void fma2(unsigned long long& d, unsigned long long a,
                                     unsigned long long b) {
    asm("fma.rn.f32x2 %0, %1, %2, %0;" : "+l"(d) : "l"(a), "l"(b));
}
__device__ __forceinline__ void mul2(unsigned long long& d, unsigned long long a) {
    asm("mul.rn.f32x2 %0, %0, %1;" : "+l"(d) : "l"(a));
}
__device__ __forceinline__ void add2(unsigned long long& d, unsigned long long a) {
    asm("add.rn.f32x2 %0, %0, %1;" : "+l"(d) : "l"(a));
}
__device__ __forceinline__ float2 unpk(unsigned long long v) {
    float2 r;
    asm("mov.b64 {%0, %1}, %2;" : "=f"(r.x), "=f"(r.y) : "l"(v));
    return r;
}
// byte k of v as biased float bits: 0x4B0000bb == 2^23 + b (exact). Bias removed
// pairwise via one add.rn.f32x2 with {-2^23, -2^23}.
__device__ __forceinline__ float prmtf(unsigned v, int k) {
    return __uint_as_float(__byte_perm(v, 0x4B000000u, 0x7540u + k));
}
__device__ __forceinline__ float warpSum(float v) {
#pragma unroll
    for (int o = 16; o; o >>= 1) v += __shfl_xor_sync(0xffffffffu, v, o);
    return v;
}
// cp.async 16B, L1-bypass (.cg): global -> shared
__device__ __forceinline__ void cpa16(unsigned saddr, const void* g) {
    asm volatile("cp.async.cg.shared.global [%0], [%1], 16;" :: "r"(saddr), "l"(g));
}
__device__ __forceinline__ void cpaCommit() { asm volatile("cp.async.commit_group;"); }
template <int n>
__device__ __forceinline__ void cpaWait() { asm volatile("cp.async.wait_group %0;" :: "n"(n)); }

// ---------------- 1. scale points, init chain-1 state ----------------
__global__ void prepK(const float* __restrict__ pc, const float* __restrict__ al) {
    int idx = blockIdx.x * blockDim.x + threadIdx.x;
    if (idx >= NP * N) return;
    int p = idx / N, i = idx - p * N;
    int b = p >> 2, k = p & 3;
    const float* xp = pc + ((size_t)b * N + i) * 3;
    float x = xp[0] * al[k * 3 + 0];
    float y = xp[1] * al[k * 3 + 1];
    float z = xp[2] * al[k * 3 + 2];
    g_Xs[p][i] = make_float4(x, y, z, x * x + y * y + z * z);
    ((float4*)&g_F[p][0])[i] = make_float4(x, y, z, 0.f);
}

// ---------------- 2. build quantized thresholded W^T (u8, diag=0) ----------------
__global__ void buildK() {
    int p = blockIdx.z;
    int i = blockIdx.x * 256 + threadIdx.x;
    int j0 = blockIdx.y * 8;
    float4 xi = g_Xs[p][i];
#pragma unroll
    for (int jj = 0; jj < 8; jj++) {
        int j = j0 + jj;
        float4 xj = g_Xs[p][j];
        float d = xi.w + xj.w - 2.f * (xi.x * xj.x + xi.y * xj.y + xi.z * xj.z);
        float w = __expf(-d * 0.1f);
        w = (w < 0.1f) ? 0.f : w;
        int q = (i == j) ? 0 : __float2int_rn(w * 127.f);
        g_W8[p][j][i] = (unsigned char)q;
    }
}

// ---------------- 3. exact degrees (fp32 exp pass; NOT from quantized W) -------
__global__ void degK() {
    int r = blockIdx.x * 8 + (threadIdx.x >> 5);   // one warp per row
    int lane = threadIdx.x & 31;
    int p = r / N, i = r - p * N;
    float4 xi = g_Xs[p][i];
    float s = 0.f;
    for (int j = lane; j < N; j += 32) {
        float4 xj = g_Xs[p][j];
        float d = xi.w + xj.w - 2.f * (xi.x * xj.x + xi.y * xj.y + xi.z * xj.z);
        float w = __expf(-d * 0.1f);
        s += (w < 0.1f) ? 0.f : w;                  // j==i contributes exp(0)=1 (self-loop)
    }
    s = warpSum(s);
    if (lane == 0) {
        g_s[p][i] = 0.5f / (127.f * s);             // row scale with dequant folded in
        g_d[p][i] = 0.5f + 0.5f / s;                // exact diagonal of P
    }
}

// ---------------- 4a. chain-1 apply (CP=4): row-pair packed dequant -------------
// 4 rows/thread as 2 row-pairs; per j: 1 LDS.32(W) + 4 PRMT + 2 ADD.f32x2 +
// 4 LDS.64(x dup) + 8 FFMA2. W staged via cp.async double buffer. x staged
// pre-duplicated {x,x}. Arithmetic lane-identical to R12 (deterministic).
__global__ void __launch_bounds__(256) apply1K(int sSrc, int sDst) {
    __shared__ __align__(16) float2 scd[JCH1 * 4];               // 2 KB duplicated x
    __shared__ __align__(16) unsigned char wbuf[2][SJ * 1024];   // 32 KB
    int p  = blockIdx.z;
    int jb = blockIdx.y * JCH1;
    int i0cta = blockIdx.x * 1024;
    int i0 = i0cta + threadIdx.x * 4;

    const unsigned char* Wp = &g_W8[p][0][0];
    auto issue = [&](int st) {
        unsigned sb = (unsigned)__cvta_generic_to_shared(&wbuf[st & 1][0]);
        const unsigned char* gb = Wp + (size_t)(jb + st * SJ) * N + i0cta;
#pragma unroll
        for (int k = 0; k < 4; k++) {
            int o = threadIdx.x + 256 * k;          // 1024 ops of 16B = 16 KB
            int r = o >> 6, c = (o & 63) << 4;
            cpa16(sb + r * 1024 + c, gb + (size_t)r * N + c);
        }
        cpaCommit();
    };
    issue(0);
    issue(1);

    // stage cur chunk duplicated (fused reduce of prev partials, fixed order)
    if (threadIdx.x < JCH1) {
        int t = threadIdx.x;
        float4 s;
        if (sSrc == 0) {
            s = ((const float4*)&g_F[p][0])[jb + t];
        } else {
            s = make_float4(0.f, 0.f, 0.f, 0.f);
#pragma unroll
            for (int jc = 0; jc < JC1; jc++) {
                float4 v = ((const float4*)&g_p1[sSrc][jc][p][0])[jb + t];
                s.x += v.x; s.y += v.y; s.z += v.z; s.w += v.w;
            }
        }
        scd[t * 4 + 0] = make_float2(s.x, s.x);
        scd[t * 4 + 1] = make_float2(s.y, s.y);
        scd[t * 4 + 2] = make_float2(s.z, s.z);
        scd[t * 4 + 3] = make_float2(s.w, s.w);
    }

    unsigned long long a[2][4];
#pragma unroll
    for (int rp = 0; rp < 2; rp++)
#pragma unroll
        for (int c = 0; c < 4; c++) a[rp][c] = 0ull;
    const unsigned long long bias = pack2(-8388608.f);

#pragma unroll
    for (int st = 0; st < NS1; st++) {
        if (st < NS1 - 1) cpaWait<1>(); else cpaWait<0>();
        __syncthreads();
        const unsigned char* wb = &wbuf[st & 1][0];
#pragma unroll
        for (int jl = 0; jl < SJ; jl++) {
            unsigned v = *(const unsigned*)(wb + jl * 1024 + threadIdx.x * 4);
            unsigned long long w01 = mkpair(prmtf(v, 0), prmtf(v, 1));
            unsigned long long w23 = mkpair(prmtf(v, 2), prmtf(v, 3));
            add2(w01, bias);
            add2(w23, bias);
            const unsigned long long* cs =
                (const unsigned long long*)(scd + (st * SJ + jl) * 4);
            fma2(a[0][0], w01, cs[0]); fma2(a[0][1], w01, cs[1]);
            fma2(a[0][2], w01, cs[2]); fma2(a[0][3], w01, cs[3]);
            fma2(a[1][0], w23, cs[0]); fma2(a[1][1], w23, cs[1]);
            fma2(a[1][2], w23, cs[2]); fma2(a[1][3], w23, cs[3]);
        }
        __syncthreads();
        if (st + 2 < NS1) issue(st + 2);
    }

    // exact row scale s_i = 0.5/(127*deg_i), packed per row-pair
#pragma unroll
    for (int rp = 0; rp < 2; rp++) {
        unsigned long long S = mkpair(g_s[p][i0 + 2 * rp], g_s[p][i0 + 2 * rp + 1]);
#pragma unroll
        for (int c = 0; c < 4; c++) mul2(a[rp][c], S);
    }

    // exact fp32 diagonal: row i gets d_i * x_i (x staged in owning chunk only)
    int jd = i0 - jb;
    if (jd >= 0 && jd < JCH1) {
#pragma unroll
        for (int rp = 0; rp < 2; rp++) {
            unsigned long long D = mkpair(g_d[p][i0 + 2 * rp], g_d[p][i0 + 2 * rp + 1]);
#pragma unroll
            for (int c = 0; c < 4; c++) {
                unsigned long long X = mkpair(scd[(jd + 2 * rp) * 4 + c].x,
                                              scd[(jd + 2 * rp + 1) * 4 + c].x);
                fma2(a[rp][c], D, X);
            }
        }
    }

    float4* o = (float4*)(&g_p1[sDst][blockIdx.y][p][0] + (size_t)i0 * 4);
#pragma unroll
    for (int rp = 0; rp < 2; rp++) {
        float2 e0 = unpk(a[rp][0]), e1 = unpk(a[rp][1]);
        float2 e2 = unpk(a[rp][2]), e3 = unpk(a[rp][3]);
        o[2 * rp]     = make_float4(e0.x, e1.x, e2.x, e3.x);
        o[2 * rp + 1] = make_float4(e0.y, e1.y, e2.y, e3.y);
    }
}

// ---------------- 4b. chain-2 apply (CP=12): NO col-split, row-pair packed ------
// Col-split removed: with cp.async covering latency, it only doubled issued
// instructions. 4 rows x 12 cols, 24 u64 accums (~70 regs, 3 CTAs/SM is fine).
__global__ void __launch_bounds__(256) apply2K(int sSrc, int sDst) {
    __shared__ __align__(16) float2 scd[JCH2 * 12];              // 12 KB duplicated x
    __shared__ __align__(16) unsigned char wbuf[2][SJ * 1024];   // 32 KB
    int p  = blockIdx.z;
    int jb = blockIdx.y * JCH2;
    int i0cta = blockIdx.x * 1024;
    int i0 = i0cta + threadIdx.x * 4;

    const unsigned char* Wp = &g_W8[p][0][0];
    auto issue = [&](int st) {
        unsigned sb = (unsigned)__cvta_generic_to_shared(&wbuf[st & 1][0]);
        const unsigned char* gb = Wp + (size_t)(jb + st * SJ) * N + i0cta;
#pragma unroll
        for (int k = 0; k < 4; k++) {
            int o = threadIdx.x + 256 * k;
            int r = o >> 6, c = (o & 63) << 4;
            cpa16(sb + r * 1024 + c, gb + (size_t)r * N + c);
        }
        cpaCommit();
    };
    issue(0);
    issue(1);

    // stage all 12 cols duplicated (fused reduce of prev partials, fixed order)
    for (int t = threadIdx.x; t < JCH2 * 3; t += 256) {
        int r = t / 3, q = t - r * 3;
        size_t off = (size_t)(jb + r) * 12 + q * 4;
        float4 s;
        if (sSrc == 0) {
            s = *(const float4*)(&g_U[p][0] + off);
        } else {
            s = make_float4(0.f, 0.f, 0.f, 0.f);
#pragma unroll
            for (int jc = 0; jc < JC2; jc++) {
                float4 v = *(const float4*)(&g_p2[sSrc][jc][p][0] + off);
                s.x += v.x; s.y += v.y; s.z += v.z; s.w += v.w;
            }
        }
        float2* dst = scd + r * 12 + q * 4;
        dst[0] = make_float2(s.x, s.x);
        dst[1] = make_float2(s.y, s.y);
        dst[2] = make_float2(s.z, s.z);
        dst[3] = make_float2(s.w, s.w);
    }

    unsigned long long a[2][12];
#pragma unroll
    for (int rp = 0; rp < 2; rp++)
#pragma unroll
        for (int c = 0; c < 12; c++) a[rp][c] = 0ull;
    const unsigned long long bias = pack2(-8388608.f);

#pragma unroll
    for (int st = 0; st < NS2; st++) {
        if (st < NS2 - 1) cpaWait<1>(); else cpaWait<0>();
        __syncthreads();
        const unsigned char* wb = &wbuf[st & 1][0];
#pragma unroll
        for (int jl = 0; jl < SJ; jl++) {
            unsigned v = *(const unsigned*)(wb + jl * 1024 + threadIdx.x * 4);
            unsigned long long w01 = mkpair(prmtf(v, 0), prmtf(v, 1));
            unsigned long long w23 = mkpair(prmtf(v, 2), prmtf(v, 3));
            add2(w01, bias);
            add2(w23, bias);
            const unsigned long long* cs =
                (const unsigned long long*)(scd + (st * SJ + jl) * 12);
#pragma unroll
            for (int c = 0; c < 12; c++) {
                unsigned long long cv = cs[c];
                fma2(a[0][c], w01, cv);
                fma2(a[1][c], w23, cv);
            }
        }
        __syncthreads();
        if (st + 2 < NS2) issue(st + 2);
    }

    // exact row scales, packed per row-pair
#pragma unroll
    for (int rp = 0; rp < 2; rp++) {
        unsigned long long S = mkpair(g_s[p][i0 + 2 * rp], g_s[p][i0 + 2 * rp + 1]);
#pragma unroll
        for (int c = 0; c < 12; c++) mul2(a[rp][c], S);
    }

    // exact fp32 diagonal (x staged in owning chunk only)
    int jd = i0 - jb;
    if (jd >= 0 && jd < JCH2) {
#pragma unroll
        for (int rp = 0; rp < 2; rp++) {
            unsigned long long D = mkpair(g_d[p][i0 + 2 * rp], g_d[p][i0 + 2 * rp + 1]);
#pragma unroll
            for (int c = 0; c < 12; c++) {
                unsigned long long X = mkpair(scd[(jd + 2 * rp) * 12 + c].x,
                                              scd[(jd + 2 * rp + 1) * 12 + c].x);
                fma2(a[rp][c], D, X);
            }
        }
    }

    float* ob = &g_p2[sDst][blockIdx.y][p][0] + (size_t)i0 * 12;
#pragma unroll
    for (int rp = 0; rp < 2; rp++) {
        float2 e[12];
#pragma unroll
        for (int c = 0; c < 12; c++) e[c] = unpk(a[rp][c]);
        float4* r0 = (float4*)(ob + (size_t)(2 * rp) * 12);
        float4* r1 = (float4*)(ob + (size_t)(2 * rp + 1) * 12);
        r0[0] = make_float4(e[0].x, e[1].x, e[2].x,  e[3].x);
        r0[1] = make_float4(e[4].x, e[5].x, e[6].x,  e[7].x);
        r0[2] = make_float4(e[8].x, e[9].x, e[10].x, e[11].x);
        r1[0] = make_float4(e[0].y, e[1].y, e[2].y,  e[3].y);
        r1[1] = make_float4(e[4].y, e[5].y, e[6].y,  e[7].y);
        r1[2] = make_float4(e[8].y, e[9].y, e[10].y, e[11].y);
    }
}

// ---------------- 5. first-order features + build U + partial output ----------------
__global__ void midK(float* __restrict__ out) {
    int p = blockIdx.x, tid = threadIdx.x;
    const int slots[5] = {1, 2, 4, 8, 16};
    float ls[18];
#pragma unroll
    for (int v = 0; v < 18; v++) ls[v] = 0.f;

    for (int i = tid; i < N; i += 256) {
        float L[6][3];
        {
            float4 f0 = ((const float4*)&g_F[p][0])[i];
            L[0][0] = f0.x; L[0][1] = f0.y; L[0][2] = f0.z;
        }
#pragma unroll
        for (int s = 0; s < 5; s++) {
            float4 acc = make_float4(0.f, 0.f, 0.f, 0.f);
#pragma unroll
            for (int jc = 0; jc < JC1; jc++) {
                float4 v = ((const float4*)&g_p1[slots[s]][jc][p][0])[i];
                acc.x += v.x; acc.y += v.y; acc.z += v.z;
            }
            L[s + 1][0] = acc.x; L[s + 1][1] = acc.y; L[s + 1][2] = acc.z;
        }
        float* U = &g_U[p][i * 12];
#pragma unroll
        for (int c = 0; c < 3; c++) {
            float u0 = fabsf(L[0][c] - L[1][c]);
            float u1 = fabsf(L[1][c] - L[2][c]);
            float u2 = fabsf(L[2][c] - L[3][c]);
            float u3 = fabsf(L[3][c] - L[4][c]);
            float u4 = fabsf(L[4][c] - L[5][c]);
            U[c] = u0; U[3 + c] = u1; U[6 + c] = u2; U[9 + c] = u3;
            ls[c]      += L[5][c];
            ls[3 + c]  += u0;  ls[6 + c]  += u1;  ls[9 + c]  += u2;
            ls[12 + c] += u3;  ls[15 + c] += u4;
        }
    }
    __shared__ float red[18][8];
    int wid = tid >> 5, lane = tid & 31;
#pragma unroll
    for (int v = 0; v < 18; v++) {
        float s = warpSum(ls[v]);
        if (lane == 0) red[v][wid] = s;
    }
    __syncthreads();
    if (tid < 18) {
        float s = 0.f;
#pragma unroll
        for (int w = 0; w < 8; w++) s += red[tid][w];
        int b = p >> 2, k = p & 3;
        out[b * 192 + k * 48 + tid] = s * (1.f / 2048.f);
    }
}

// ---------------- 6. second-order features + remaining output ----------------
__global__ void finalK(float* __restrict__ out) {
    int p = blockIdx.x, tid = threadIdx.x;
    const int slots[5] = {1, 2, 4, 8, 16};
    float ls[30];
#pragma unroll
    for (int v = 0; v < 30; v++) ls[v] = 0.f;

    for (int i = tid; i < N; i += 256) {
        float A[5][12];
#pragma unroll
        for (int s = 0; s < 5; s++) {
#pragma unroll
            for (int q = 0; q < 3; q++) {
                float4 acc = make_float4(0.f, 0.f, 0.f, 0.f);
#pragma unroll
                for (int jc = 0; jc < JC2; jc++) {
                    float4 v = ((const float4*)&g_p2[slots[s]][jc][p][0])[i * 3 + q];
                    acc.x += v.x; acc.y += v.y; acc.z += v.z; acc.w += v.w;
                }
                A[s][4 * q + 0] = acc.x; A[s][4 * q + 1] = acc.y;
                A[s][4 * q + 2] = acc.z; A[s][4 * q + 3] = acc.w;
            }
        }
#pragma unroll
        for (int c = 0; c < 3;  c++) ls[c]      += fabsf(A[0][c] - A[1][c]);
#pragma unroll
        for (int c = 0; c < 6;  c++) ls[3 + c]  += fabsf(A[1][c] - A[2][c]);
#pragma unroll
        for (int c = 0; c < 9;  c++) ls[9 + c]  += fabsf(A[2][c] - A[3][c]);
#pragma unroll
        for (int c = 0; c < 12; c++) ls[18 + c] += fabsf(A[3][c] - A[4][c]);
    }
    __shared__ float red[30][8];
    int wid = tid >> 5, lane = tid & 31;
#pragma unroll
    for (int v = 0; v < 30; v++) {
        float s = warpSum(ls[v]);
        if (lane == 0) red[v][wid] = s;
    }
    __syncthreads();
    if (tid < 30) {
        float s = 0.f;
#pragma unroll
        for (int w = 0; w < 8; w++) s += red[tid][w];
        int b = p >> 2, k = p & 3;
        out[b * 192 + k * 48 + 18 + tid] = s * (1.f / 2048.f);
    }
}

// ---------------- launch ----------------
extern "C" void kernel_launch(void* const* d_in, const int* in_sizes, int n_in,
                              void* d_out, int out_size) {
    (void)in_sizes; (void)n_in; (void)out_size;
    const float* pc = (const float*)d_in[0];   // [4,2048,3]
    const float* al = (const float*)d_in[1];   // [4,3]
    float* out = (float*)d_out;                // [768]

    prepK<<<(NP * N + 255) / 256, 256>>>(pc, al);
    buildK<<<dim3(N / 256, N / 8, NP), 256>>>();
    degK<<<NP * N / 8, 256>>>();

    for (int s = 1; s <= 16; s++)
        apply1K<<<dim3(2, JC1, NP), 256>>>(s - 1, s);

    midK<<<NP, 256>>>(out);

    for (int s = 1; s <= 16; s++)
        apply2K<<<dim3(2, JC2, NP), 256>>>(s - 1, s);

    finalK<<<NP, 256>>>(out);
}

// round 14
// speedup vs baseline: 1.0815x; 1.0815x over previous
#include <cuda_runtime.h>

#define NP   16     // B*K problems
#define N    2048   // points per cloud
#define JC1  32     // j-chunks, chain 1 (CP=4)
#define JCH1 (N / JC1)
#define JC2  16     // j-chunks, chain 2 (CP=12)
#define JCH2 (N / JC2)
#define SJ   16     // j rows per cp.async stage
#define NS1  (JCH1 / SJ)   // 4 stages, chain 1
#define NS2  (JCH2 / SJ)   // 8 stages, chain 2

// ---------------- scratch (__device__ globals: allocation-free) ----------------
__device__ float4        g_Xs[NP][N];               // scaled points + squared norm
__device__ unsigned char g_W8[NP][N][N];            // q=round(127*w), u8, diag=0; transposed (i fastest)
__device__ float         g_s[NP][N];                // s_i = 0.5/(127*deg_i)  (dequant folded in)
__device__ float         g_d[NP][N];                // d_i = 0.5 + 0.5/deg_i  (exact diagonal of P)
__device__ float         g_F[NP][N * 4];            // chain-1 t=0 (x,y,z,0)
__device__ float         g_U[NP][N * 12];           // chain-2 t=0 (first 12 cols of U)
__device__ float         g_p1[17][JC1][NP][N * 4];  // chain-1 per-step j-chunk partials
__device__ float         g_p2[17][JC2][NP][N * 12]; // chain-2 per-step j-chunk partials

// ---------------- helpers ----------------
__device__ __forceinline__ unsigned long long pack2(float a) {
    unsigned long long r;
    asm("mov.b64 %0, {%1, %1};" : "=l"(r) : "f"(a));
    return r;
}
__device__ __forceinline__ void fma2(unsigned long long& d, unsigned long long a,
                                     unsigned long long b) {
    asm("fma.rn.f32x2 %0, %1, %2, %0;" : "+l"(d) : "l"(a), "l"(b));
}
__device__ __forceinline__ void mul2(unsigned long long& d, unsigned long long a) {
    asm("mul.rn.f32x2 %0, %0, %1;" : "+l"(d) : "l"(a));
}
__device__ __forceinline__ float2 unpk(unsigned long long v) {
    float2 r;
    asm("mov.b64 {%0, %1}, %2;" : "=f"(r.x), "=f"(r.y) : "l"(v));
    return r;
}
// byte k of v -> exact float in [0,255]: PRMT builds 0x4B0000bb (= 2^23 + b), FADD subtracts
__device__ __forceinline__ float b2f(unsigned v, int k) {
    return __uint_as_float(__byte_perm(v, 0x4B000000u, 0x7540u + k)) - 8388608.f;
}
__device__ __forceinline__ float warpSum(float v) {
#pragma unroll
    for (int o = 16; o; o >>= 1) v += __shfl_xor_sync(0xffffffffu, v, o);
    return v;
}
// cp.async 16B, L1-bypass (.cg): global -> shared
__device__ __forceinline__ void cpa16(unsigned saddr, const void* g) {
    asm volatile("cp.async.cg.shared.global [%0], [%1], 16;" :: "r"(saddr), "l"(g));
}
__device__ __forceinline__ void cpaCommit() { asm volatile("cp.async.commit_group;"); }
template <int n>
__device__ __forceinline__ void cpaWait() { asm volatile("cp.async.wait_group %0;" :: "n"(n)); }

// ---------------- 1. scale points, init chain-1 state ----------------
__global__ void prepK(const float* __restrict__ pc, const float* __restrict__ al) {
    int idx = blockIdx.x * blockDim.x + threadIdx.x;
    if (idx >= NP * N) return;
    int p = idx / N, i = idx - p * N;
    int b = p >> 2, k = p & 3;
    const float* xp = pc + ((size_t)b * N + i) * 3;
    float x = xp[0] * al[k * 3 + 0];
    float y = xp[1] * al[k * 3 + 1];
    float z = xp[2] * al[k * 3 + 2];
    g_Xs[p][i] = make_float4(x, y, z, x * x + y * y + z * z);
    ((float4*)&g_F[p][0])[i] = make_float4(x, y, z, 0.f);
}

// ---------------- 2. build quantized thresholded W^T (u8, diag=0) ----------------
__global__ void buildK() {
    int p = blockIdx.z;
    int i = blockIdx.x * 256 + threadIdx.x;
    int j0 = blockIdx.y * 8;
    float4 xi = g_Xs[p][i];
#pragma unroll
    for (int jj = 0; jj < 8; jj++) {
        int j = j0 + jj;
        float4 xj = g_Xs[p][j];
        float d = xi.w + xj.w - 2.f * (xi.x * xj.x + xi.y * xj.y + xi.z * xj.z);
        float w = __expf(-d * 0.1f);
        w = (w < 0.1f) ? 0.f : w;
        int q = (i == j) ? 0 : __float2int_rn(w * 127.f);
        g_W8[p][j][i] = (unsigned char)q;
    }
}

// ---------------- 3. exact degrees (fp32 exp pass; NOT from quantized W) -------
__global__ void degK() {
    int r = blockIdx.x * 8 + (threadIdx.x >> 5);   // one warp per row
    int lane = threadIdx.x & 31;
    int p = r / N, i = r - p * N;
    float4 xi = g_Xs[p][i];
    float s = 0.f;
    for (int j = lane; j < N; j += 32) {
        float4 xj = g_Xs[p][j];
        float d = xi.w + xj.w - 2.f * (xi.x * xj.x + xi.y * xj.y + xi.z * xj.z);
        float w = __expf(-d * 0.1f);
        s += (w < 0.1f) ? 0.f : w;                  // j==i contributes exp(0)=1 (self-loop)
    }
    s = warpSum(s);
    if (lane == 0) {
        g_s[p][i] = 0.5f / (127.f * s);             // row scale with dequant folded in
        g_d[p][i] = 0.5f + 0.5f / s;                // exact diagonal of P
    }
}

// ---------------- 4a. chain-1 apply (CP=4), cp.async double-buffered W ----------
// EXACT R12 version (proven 22.5us): 4 rows/thread, dup-w dequant, 2 LDS.64 x.
__global__ void __launch_bounds__(256) apply1K(int sSrc, int sDst) {
    __shared__ __align__(16) float sc[JCH1 * 4];                 // 1 KB
    __shared__ __align__(16) unsigned char wbuf[2][SJ * 1024];   // 32 KB
    int p  = blockIdx.z;
    int jb = blockIdx.y * JCH1;
    int i0cta = blockIdx.x * 1024;
    int i0 = i0cta + threadIdx.x * 4;

    const unsigned char* Wp = &g_W8[p][0][0];
    auto issue = [&](int st) {
        unsigned sb = (unsigned)__cvta_generic_to_shared(&wbuf[st & 1][0]);
        const unsigned char* gb = Wp + (size_t)(jb + st * SJ) * N + i0cta;
#pragma unroll
        for (int k = 0; k < 4; k++) {
            int o = threadIdx.x + 256 * k;          // 1024 ops of 16B = 16 KB
            int r = o >> 6, c = (o & 63) << 4;
            cpa16(sb + r * 1024 + c, gb + (size_t)r * N + c);
        }
        cpaCommit();
    };
    issue(0);
    issue(1);

    // stage cur chunk (fused reduce of prev partials, fixed order)
    if (threadIdx.x < JCH1) {
        int t = threadIdx.x;
        float4 s;
        if (sSrc == 0) {
            s = ((const float4*)&g_F[p][0])[jb + t];
        } else {
            s = make_float4(0.f, 0.f, 0.f, 0.f);
#pragma unroll
            for (int jc = 0; jc < JC1; jc++) {
                float4 v = ((const float4*)&g_p1[sSrc][jc][p][0])[jb + t];
                s.x += v.x; s.y += v.y; s.z += v.z; s.w += v.w;
            }
        }
        ((float4*)sc)[t] = s;
    }

    unsigned long long a[4][2];
#pragma unroll
    for (int r = 0; r < 4; r++) { a[r][0] = 0ull; a[r][1] = 0ull; }

#pragma unroll
    for (int st = 0; st < NS1; st++) {
        if (st < NS1 - 1) cpaWait<1>(); else cpaWait<0>();
        __syncthreads();
        const unsigned char* wb = &wbuf[st & 1][0];
#pragma unroll
        for (int jl = 0; jl < SJ; jl++) {
            unsigned v = *(const unsigned*)(wb + jl * 1024 + threadIdx.x * 4);
            unsigned long long p0 = pack2(b2f(v, 0));
            unsigned long long p1 = pack2(b2f(v, 1));
            unsigned long long p2 = pack2(b2f(v, 2));
            unsigned long long p3 = pack2(b2f(v, 3));
            const unsigned long long* cs =
                (const unsigned long long*)(sc + (st * SJ + jl) * 4);
            unsigned long long c0 = cs[0], c1 = cs[1];
            fma2(a[0][0], p0, c0); fma2(a[0][1], p0, c1);
            fma2(a[1][0], p1, c0); fma2(a[1][1], p1, c1);
            fma2(a[2][0], p2, c0); fma2(a[2][1], p2, c1);
            fma2(a[3][0], p3, c0); fma2(a[3][1], p3, c1);
        }
        __syncthreads();
        if (st + 2 < NS1) issue(st + 2);
    }

    // exact row scale s_i = 0.5/(127*deg_i)
#pragma unroll
    for (int r = 0; r < 4; r++) {
        unsigned long long S = pack2(g_s[p][i0 + r]);
        mul2(a[r][0], S); mul2(a[r][1], S);
    }

    // exact fp32 diagonal: row i gets d_i * x_i (x staged in owning chunk only)
    int jd = i0 - jb;
    if (jd >= 0 && jd < JCH1) {
#pragma unroll
        for (int r = 0; r < 4; r++) {
            unsigned long long D = pack2(g_d[p][i0 + r]);
            const unsigned long long* csd = (const unsigned long long*)(sc + (jd + r) * 4);
            fma2(a[r][0], D, csd[0]); fma2(a[r][1], D, csd[1]);
        }
    }

    float4* o = (float4*)(&g_p1[sDst][blockIdx.y][p][0] + (size_t)i0 * 4);
#pragma unroll
    for (int r = 0; r < 4; r++) {
        float2 lo = unpk(a[r][0]), hi = unpk(a[r][1]);
        o[r] = make_float4(lo.x, lo.y, hi.x, hi.y);
    }
}

// ---------------- 4b. chain-2 apply (CP=12): full 12 cols, R12-style dequant ----
// Col-split removed (it duplicated W load + dequant across half-CTAs); dequant
// kept in the proven R12 shape (dup-w MOV, non-duplicated x via 6 LDS.64).
// 43 issue slots per 24 FFMA2 vs col-split's 56. cp.async covers 3-CTA/SM occ.
__global__ void __launch_bounds__(256) apply2K(int sSrc, int sDst) {
    __shared__ __align__(16) float sc[JCH2 * 12];                // 6 KB
    __shared__ __align__(16) unsigned char wbuf[2][SJ * 1024];   // 32 KB
    int p  = blockIdx.z;
    int jb = blockIdx.y * JCH2;
    int i0cta = blockIdx.x * 1024;
    int i0 = i0cta + threadIdx.x * 4;

    const unsigned char* Wp = &g_W8[p][0][0];
    auto issue = [&](int st) {
        unsigned sb = (unsigned)__cvta_generic_to_shared(&wbuf[st & 1][0]);
        const unsigned char* gb = Wp + (size_t)(jb + st * SJ) * N + i0cta;
#pragma unroll
        for (int k = 0; k < 4; k++) {
            int o = threadIdx.x + 256 * k;
            int r = o >> 6, c = (o & 63) << 4;
            cpa16(sb + r * 1024 + c, gb + (size_t)r * N + c);
        }
        cpaCommit();
    };
    issue(0);
    issue(1);

    // stage all 12 cols of cur chunk (fused reduce of prev partials, fixed order)
    for (int t = threadIdx.x; t < JCH2 * 3; t += 256) {
        int r = t / 3, q = t - r * 3;
        size_t off = (size_t)(jb + r) * 12 + q * 4;
        float4 s;
        if (sSrc == 0) {
            s = *(const float4*)(&g_U[p][0] + off);
        } else {
            s = make_float4(0.f, 0.f, 0.f, 0.f);
#pragma unroll
            for (int jc = 0; jc < JC2; jc++) {
                float4 v = *(const float4*)(&g_p2[sSrc][jc][p][0] + off);
                s.x += v.x; s.y += v.y; s.z += v.z; s.w += v.w;
            }
        }
        *(float4*)(sc + r * 12 + q * 4) = s;
    }

    unsigned long long a0[6], a1[6], a2[6], a3[6];
#pragma unroll
    for (int c = 0; c < 6; c++) { a0[c] = 0ull; a1[c] = 0ull; a2[c] = 0ull; a3[c] = 0ull; }

#pragma unroll
    for (int st = 0; st < NS2; st++) {
        if (st < NS2 - 1) cpaWait<1>(); else cpaWait<0>();
        __syncthreads();
        const unsigned char* wb = &wbuf[st & 1][0];
#pragma unroll
        for (int jl = 0; jl < SJ; jl++) {
            unsigned v = *(const unsigned*)(wb + jl * 1024 + threadIdx.x * 4);
            unsigned long long p0 = pack2(b2f(v, 0));
            unsigned long long p1 = pack2(b2f(v, 1));
            unsigned long long p2 = pack2(b2f(v, 2));
            unsigned long long p3 = pack2(b2f(v, 3));
            const unsigned long long* cs =
                (const unsigned long long*)(sc + (st * SJ + jl) * 12);
#pragma unroll
            for (int c = 0; c < 6; c++) {
                unsigned long long cv = cs[c];
                fma2(a0[c], p0, cv);
                fma2(a1[c], p1, cv);
                fma2(a2[c], p2, cv);
                fma2(a3[c], p3, cv);
            }
        }
        __syncthreads();
        if (st + 2 < NS2) issue(st + 2);
    }

    // exact row scales
    {
        unsigned long long S0 = pack2(g_s[p][i0]);
        unsigned long long S1 = pack2(g_s[p][i0 + 1]);
        unsigned long long S2 = pack2(g_s[p][i0 + 2]);
        unsigned long long S3 = pack2(g_s[p][i0 + 3]);
#pragma unroll
        for (int c = 0; c < 6; c++) {
            mul2(a0[c], S0); mul2(a1[c], S1); mul2(a2[c], S2); mul2(a3[c], S3);
        }
    }

    // exact fp32 diagonal (x staged in owning chunk only)
    int jd = i0 - jb;
    if (jd >= 0 && jd < JCH2) {
        unsigned long long D0 = pack2(g_d[p][i0]);
        unsigned long long D1 = pack2(g_d[p][i0 + 1]);
        unsigned long long D2 = pack2(g_d[p][i0 + 2]);
        unsigned long long D3 = pack2(g_d[p][i0 + 3]);
        const unsigned long long* d0 = (const unsigned long long*)(sc + jd * 12);
        const unsigned long long* d1 = (const unsigned long long*)(sc + (jd + 1) * 12);
        const unsigned long long* d2 = (const unsigned long long*)(sc + (jd + 2) * 12);
        const unsigned long long* d3 = (const unsigned long long*)(sc + (jd + 3) * 12);
#pragma unroll
        for (int c = 0; c < 6; c++) {
            fma2(a0[c], D0, d0[c]);
            fma2(a1[c], D1, d1[c]);
            fma2(a2[c], D2, d2[c]);
            fma2(a3[c], D3, d3[c]);
        }
    }

    float* ob = &g_p2[sDst][blockIdx.y][p][0] + (size_t)i0 * 12;
#pragma unroll
    for (int r = 0; r < 4; r++) {
        unsigned long long* ar = (r == 0) ? a0 : (r == 1) ? a1 : (r == 2) ? a2 : a3;
        float2 e[6];
#pragma unroll
        for (int c = 0; c < 6; c++) e[c] = unpk(ar[c]);
        float4* orow = (float4*)(ob + (size_t)r * 12);
        orow[0] = make_float4(e[0].x, e[0].y, e[1].x, e[1].y);
        orow[1] = make_float4(e[2].x, e[2].y, e[3].x, e[3].y);
        orow[2] = make_float4(e[4].x, e[4].y, e[5].x, e[5].y);
    }
}

// ---------------- 5. first-order features + build U + partial output ----------------
__global__ void midK(float* __restrict__ out) {
    int p = blockIdx.x, tid = threadIdx.x;
    const int slots[5] = {1, 2, 4, 8, 16};
    float ls[18];
#pragma unroll
    for (int v = 0; v < 18; v++) ls[v] = 0.f;

    for (int i = tid; i < N; i += 256) {
        float L[6][3];
        {
            float4 f0 = ((const float4*)&g_F[p][0])[i];
            L[0][0] = f0.x; L[0][1] = f0.y; L[0][2] = f0.z;
        }
#pragma unroll
        for (int s = 0; s < 5; s++) {
            float4 acc = make_float4(0.f, 0.f, 0.f, 0.f);
#pragma unroll
            for (int jc = 0; jc < JC1; jc++) {
                float4 v = ((const float4*)&g_p1[slots[s]][jc][p][0])[i];
                acc.x += v.x; acc.y += v.y; acc.z += v.z;
            }
            L[s + 1][0] = acc.x; L[s + 1][1] = acc.y; L[s + 1][2] = acc.z;
        }
        float* U = &g_U[p][i * 12];
#pragma unroll
        for (int c = 0; c < 3; c++) {
            float u0 = fabsf(L[0][c] - L[1][c]);
            float u1 = fabsf(L[1][c] - L[2][c]);
            float u2 = fabsf(L[2][c] - L[3][c]);
            float u3 = fabsf(L[3][c] - L[4][c]);
            float u4 = fabsf(L[4][c] - L[5][c]);
            U[c] = u0; U[3 + c] = u1; U[6 + c] = u2; U[9 + c] = u3;
            ls[c]      += L[5][c];
            ls[3 + c]  += u0;  ls[6 + c]  += u1;  ls[9 + c]  += u2;
            ls[12 + c] += u3;  ls[15 + c] += u4;
        }
    }
    __shared__ float red[18][8];
    int wid = tid >> 5, lane = tid & 31;
#pragma unroll
    for (int v = 0; v < 18; v++) {
        float s = warpSum(ls[v]);
        if (lane == 0) red[v][wid] = s;
    }
    __syncthreads();
    if (tid < 18) {
        float s = 0.f;
#pragma unroll
        for (int w = 0; w < 8; w++) s += red[tid][w];
        int b = p >> 2, k = p & 3;
        out[b * 192 + k * 48 + tid] = s * (1.f / 2048.f);
    }
}

// ---------------- 6. second-order features + remaining output ----------------
__global__ void finalK(float* __restrict__ out) {
    int p = blockIdx.x, tid = threadIdx.x;
    const int slots[5] = {1, 2, 4, 8, 16};
    float ls[30];
#pragma unroll
    for (int v = 0; v < 30; v++) ls[v] = 0.f;

    for (int i = tid; i < N; i += 256) {
        float A[5][12];
#pragma unroll
        for (int s = 0; s < 5; s++) {
#pragma unroll
            for (int q = 0; q < 3; q++) {
                float4 acc = make_float4(0.f, 0.f, 0.f, 0.f);
#pragma unroll
                for (int jc = 0; jc < JC2; jc++) {
                    float4 v = ((const float4*)&g_p2[slots[s]][jc][p][0])[i * 3 + q];
                    acc.x += v.x; acc.y += v.y; acc.z += v.z; acc.w += v.w;
                }
                A[s][4 * q + 0] = acc.x; A[s][4 * q + 1] = acc.y;
                A[s][4 * q + 2] = acc.z; A[s][4 * q + 3] = acc.w;
            }
        }
#pragma unroll
        for (int c = 0; c < 3;  c++) ls[c]      += fabsf(A[0][c] - A[1][c]);
#pragma unroll
        for (int c = 0; c < 6;  c++) ls[3 + c]  += fabsf(A[1][c] - A[2][c]);
#pragma unroll
        for (int c = 0; c < 9;  c++) ls[9 + c]  += fabsf(A[2][c] - A[3][c]);
#pragma unroll
        for (int c = 0; c < 12; c++) ls[18 + c] += fabsf(A[3][c] - A[4][c]);
    }
    __shared__ float red[30][8];
    int wid = tid >> 5, lane = tid & 31;
#pragma unroll
    for (int v = 0; v < 30; v++) {
        float s = warpSum(ls[v]);
        if (lane == 0) red[v][wid] = s;
    }
    __syncthreads();
    if (tid < 30) {
        float s = 0.f;
#pragma unroll
        for (int w = 0; w < 8; w++) s += red[tid][w];
        int b = p >> 2, k = p & 3;
        out[b * 192 + k * 48 + 18 + tid] = s * (1.f / 2048.f);
    }
}

// ---------------- launch ----------------
extern "C" void kernel_launch(void* const* d_in, const int* in_sizes, int n_in,
                              void* d_out, int out_size) {
    (void)in_sizes; (void)n_in; (void)out_size;
    const float* pc = (const float*)d_in[0];   // [4,2048,3]
    const float* al = (const float*)d_in[1];   // [4,3]
    float* out = (float*)d_out;                // [768]

    prepK<<<(NP * N + 255) / 256, 256>>>(pc, al);
    buildK<<<dim3(N / 256, N / 8, NP), 256>>>();
    degK<<<NP * N / 8, 256>>>();

    for (int s = 1; s <= 16; s++)
        apply1K<<<dim3(2, JC1, NP), 256>>>(s - 1, s);

    midK<<<NP, 256>>>(out);

    for (int s = 1; s <= 16; s++)
        apply2K<<<dim3(2, JC2, NP), 256>>>(s - 1, s);

    finalK<<<NP, 256>>>(out);
}